// round 2
// baseline (speedup 1.0000x reference)
#include <cuda_runtime.h>

#define NELEM 589824      // 64*96*96
#define BATCH 2
#define TOPK  2048
#define CAP   4096        // candidate capacity (expected ~2150 for this input)
#define NBINS 65536

// ---------------- device scratch (no allocations allowed) ----------------
__device__ unsigned int        g_hist[BATCH][NBINS];
__device__ int                 g_cnt[BATCH];
__device__ int                 g_bstar[BATCH];
__device__ unsigned long long  g_cand[BATCH][CAP];
__device__ float               g_out7[BATCH][TOPK][7];
__device__ float               g_lo[BATCH][TOPK][3];
__device__ float               g_hi[BATCH][TOPK][3];
__device__ float               g_vol[BATCH][TOPK];
__device__ unsigned long long  g_mask[BATCH][TOPK][32];
__device__ unsigned long long  g_keep[BATCH][32];

// monotonic key: descending float order == descending unsigned order
__device__ __forceinline__ unsigned int fkey(float f) {
    unsigned int b = __float_as_uint(f);
    unsigned int m = ((unsigned int)((int)b >> 31)) | 0x80000000u;
    return b ^ m;
}

// ---------------- 1. zero ----------------
__global__ void k_zero() {
    int i = blockIdx.x * blockDim.x + threadIdx.x;
    int tot = BATCH * NBINS;
    for (; i < tot; i += gridDim.x * blockDim.x)
        ((unsigned int*)g_hist)[i] = 0u;
    if (blockIdx.x == 0 && threadIdx.x < BATCH) g_cnt[threadIdx.x] = 0;
}

// ---------------- 2. histogram over top-16-bit key ----------------
__global__ void k_hist(const float* __restrict__ scores) {
    int i = blockIdx.x * blockDim.x + threadIdx.x;
    if (i >= BATCH * NELEM) return;
    int b = i / NELEM;
    atomicAdd(&g_hist[b][fkey(scores[i]) >> 16], 1u);
}

// ---------------- 3. find threshold bin (1 block / batch) ----------------
__global__ void k_selbin() {
    __shared__ unsigned int sh[1024];
    __shared__ unsigned int red[1024];
    __shared__ unsigned int cum;
    __shared__ int found;
    int b = blockIdx.x, t = threadIdx.x;
    if (t == 0) { cum = 0; found = 0; }
    __syncthreads();
    for (int chunk = 63; chunk >= 0; --chunk) {
        unsigned v = g_hist[b][chunk * 1024 + t];
        sh[t] = v; red[t] = v;
        __syncthreads();
        for (int s = 512; s > 0; s >>= 1) {
            if (t < s) red[t] += red[t + s];
            __syncthreads();
        }
        if (t == 0) {
            unsigned total = red[0];
            if (cum + total < TOPK) {
                cum += total;
            } else {
                unsigned c = cum;
                for (int i = 1023; i >= 0; --i) {
                    c += sh[i];
                    if (c >= TOPK) { g_bstar[b] = chunk * 1024 + i; found = 1; break; }
                }
            }
        }
        __syncthreads();
        if (found) break;
    }
}

// ---------------- 4. gather candidates ----------------
__global__ void k_gather(const float* __restrict__ scores) {
    int i = blockIdx.x * blockDim.x + threadIdx.x;
    if (i >= BATCH * NELEM) return;
    int b = i / NELEM;
    int p = i - b * NELEM;
    unsigned u = fkey(scores[i]);
    if ((int)(u >> 16) >= g_bstar[b]) {
        int pos = atomicAdd(&g_cnt[b], 1);
        if (pos < CAP)
            g_cand[b][pos] = ((unsigned long long)u << 32) | (unsigned int)(~(unsigned int)p);
    }
}

// ---------------- 5. bitonic sort 4096 keys descending (1 block / batch) ----------------
__global__ void k_sort() {
    __shared__ unsigned long long sk[CAP];
    int b = blockIdx.x, t = threadIdx.x;
    int cnt = g_cnt[b]; if (cnt > CAP) cnt = CAP;
    for (int i = t; i < CAP; i += blockDim.x)
        sk[i] = (i < cnt) ? g_cand[b][i] : 0ULL;
    __syncthreads();
    for (int k = 2; k <= CAP; k <<= 1) {
        for (int j = k >> 1; j > 0; j >>= 1) {
            for (int i = t; i < CAP; i += blockDim.x) {
                int l = i ^ j;
                if (l > i) {
                    unsigned long long a = sk[i], c = sk[l];
                    bool desc = ((i & k) == 0);
                    if (desc ? (a < c) : (a > c)) { sk[i] = c; sk[l] = a; }
                }
            }
            __syncthreads();
        }
    }
    for (int i = t; i < TOPK; i += blockDim.x) g_cand[b][i] = sk[i];
}

// ---------------- 6. deparametrize selected boxes only ----------------
__global__ void k_boxes(const float* __restrict__ bboxes, const float* __restrict__ scores) {
    int r = blockIdx.x * blockDim.x + threadIdx.x;
    if (r >= BATCH * TOPK) return;
    int b = r / TOPK;
    int row = r - b * TOPK;
    unsigned long long key = g_cand[b][row];
    unsigned int idx = ~(unsigned int)(key & 0xFFFFFFFFu);
    int d = idx / 9216;
    int rem = idx - d * 9216;
    int h = rem / 96;
    int w = rem - h * 96;
    float coord[3] = { (float)d + 0.5f, (float)h + 0.5f, (float)w + 0.5f };
    const float* bb = bboxes + (size_t)b * 6 * NELEM + idx;
    g_out7[b][row][0] = scores[(size_t)b * NELEM + idx];
    float vol = 1.0f;
#pragma unroll
    for (int c = 0; c < 3; c++) {
        float ctr = bb[(size_t)c * NELEM] * 12.0f + coord[c];
        float sz  = expf(bb[(size_t)(c + 3) * NELEM]) * 12.0f;
        g_out7[b][row][1 + c] = ctr;
        g_out7[b][row][4 + c] = sz;
        float half = sz * 0.5f;
        g_lo[b][row][c] = ctr - half;
        g_hi[b][row][c] = ctr + half;
        vol *= sz;
    }
    g_vol[b][row] = vol;
}

// ---------------- 7. IoU suppression bitmask ----------------
__global__ void k_mask() {
    int jw = blockIdx.x, itile = blockIdx.y, b = blockIdx.z;
    int t = threadIdx.x;
    int i = itile * 64 + t;
    if (jw < itile) { g_mask[b][i][jw] = 0ULL; return; }
    __shared__ float slo[64][3], shi[64][3], svol[64];
    int j0 = jw * 64;
#pragma unroll
    for (int c = 0; c < 3; c++) {
        slo[t][c] = g_lo[b][j0 + t][c];
        shi[t][c] = g_hi[b][j0 + t][c];
    }
    svol[t] = g_vol[b][j0 + t];
    __syncthreads();
    float lo0 = g_lo[b][i][0], lo1 = g_lo[b][i][1], lo2 = g_lo[b][i][2];
    float hi0 = g_hi[b][i][0], hi1 = g_hi[b][i][1], hi2 = g_hi[b][i][2];
    float voli = g_vol[b][i];
    unsigned long long bits = 0ULL;
#pragma unroll 8
    for (int jj = 0; jj < 64; jj++) {
        int j = j0 + jj;
        float t0 = fmaxf(fminf(hi0, shi[jj][0]) - fmaxf(lo0, slo[jj][0]), 0.0f);
        float t1 = fmaxf(fminf(hi1, shi[jj][1]) - fmaxf(lo1, slo[jj][1]), 0.0f);
        float t2 = fmaxf(fminf(hi2, shi[jj][2]) - fmaxf(lo2, slo[jj][2]), 0.0f);
        float inter = t0 * t1 * t2;
        float uni = voli + svol[jj] - inter;
        if ((j > i) && (inter / uni > 0.25f)) bits |= (1ULL << jj);
    }
    g_mask[b][i][jw] = bits;
}

// ---------------- 8. serial greedy NMS reduce (1 warp / batch) ----------------
__global__ void k_reduce() {
    int b = blockIdx.x;
    int lane = threadIdx.x;            // 0..31, owns word `lane`
    unsigned long long remv = 0ULL;
    for (int w = 0; w < 32; ++w) {
        // replicate current word's suppression state across all lanes
        unsigned long long rw = __shfl_sync(0xFFFFFFFFu, remv, w);
#pragma unroll 8
        for (int bit = 0; bit < 64; ++bit) {
            int i = w * 64 + bit;
            unsigned long long m = g_mask[b][i][lane];            // prefetchable
            unsigned long long mw = __shfl_sync(0xFFFFFFFFu, m, w);
            bool alive = !((rw >> bit) & 1ULL);
            if (alive) { remv |= m; rw |= mw; }
        }
    }
    g_keep[b][lane] = ~remv;
}

// ---------------- 9. write output ----------------
__global__ void k_out(float* __restrict__ out) {
    int r = blockIdx.x * blockDim.x + threadIdx.x;
    if (r >= BATCH * TOPK) return;
    int b = r / TOPK;
    int row = r - b * TOPK;
    bool keep = (g_keep[b][row >> 6] >> (row & 63)) & 1ULL;
    float* o = out + (size_t)r * 7;
#pragma unroll
    for (int c = 0; c < 7; c++) o[c] = keep ? g_out7[b][row][c] : 0.0f;
}

extern "C" void kernel_launch(void* const* d_in, const int* in_sizes, int n_in,
                              void* d_out, int out_size) {
    const float* bboxes = (const float*)d_in[0];   // (2,6,64,96,96)
    const float* scores = (const float*)d_in[1];   // (2,64,96,96)
    float* out = (float*)d_out;                    // (2,2048,7)

    int total = BATCH * NELEM;
    int gb = (total + 511) / 512;

    k_zero<<<256, 512>>>();
    k_hist<<<gb, 512>>>(scores);
    k_selbin<<<BATCH, 1024>>>();
    k_gather<<<gb, 512>>>(scores);
    k_sort<<<BATCH, 1024>>>();
    k_boxes<<<(BATCH * TOPK + 255) / 256, 256>>>(bboxes, scores);
    k_mask<<<dim3(32, 32, BATCH), 64>>>();
    k_reduce<<<BATCH, 32>>>();
    k_out<<<(BATCH * TOPK + 255) / 256, 256>>>(out);
}

// round 3
// speedup vs baseline: 1.3985x; 1.3985x over previous
#include <cuda_runtime.h>

#define NELEM 589824      // 64*96*96
#define NVEC4 147456      // NELEM/4
#define BATCH 2
#define TOPK  2048
#define CAP   4096
#define NBINS 4096        // top-12-bit key histogram

// ---------------- device scratch ----------------
__device__ unsigned int        g_hist[BATCH][NBINS];
__device__ int                 g_cnt[BATCH];
__device__ int                 g_bstar[BATCH];
__device__ unsigned long long  g_cand[BATCH][CAP];
__device__ float               g_out7[BATCH][TOPK][7];
__device__ float               g_lo[BATCH][TOPK][3];
__device__ float               g_hi[BATCH][TOPK][3];
__device__ float               g_vol[BATCH][TOPK];
__device__ unsigned long long  g_mask[BATCH][32][TOPK];   // [word][row] transposed

__device__ __forceinline__ unsigned int fkey(float f) {
    unsigned int b = __float_as_uint(f);
    unsigned int m = ((unsigned int)((int)b >> 31)) | 0x80000000u;
    return b ^ m;
}
__device__ __forceinline__ float fkey_inv(unsigned int u) {
    unsigned int b = (u & 0x80000000u) ? (u ^ 0x80000000u) : ~u;
    return __uint_as_float(b);
}

// ---------------- 1. zero ----------------
__global__ void k_zero() {
    int i = blockIdx.x * blockDim.x + threadIdx.x;
    int tot = BATCH * NBINS;
    for (; i < tot; i += gridDim.x * blockDim.x)
        ((unsigned int*)g_hist)[i] = 0u;
    if (blockIdx.x == 0 && threadIdx.x < BATCH) g_cnt[threadIdx.x] = 0;
}

// ---------------- 2. privatized 4096-bin histogram ----------------
__global__ void k_hist(const float* __restrict__ scores) {
    __shared__ unsigned int sh[NBINS];
    int t = threadIdx.x;
    for (int i = t; i < NBINS; i += blockDim.x) sh[i] = 0u;
    __syncthreads();
    int b = blockIdx.y;
    const float4* s = (const float4*)(scores + (size_t)b * NELEM);
    for (int i = blockIdx.x * blockDim.x + t; i < NVEC4; i += gridDim.x * blockDim.x) {
        float4 v = s[i];
        atomicAdd(&sh[fkey(v.x) >> 20], 1u);
        atomicAdd(&sh[fkey(v.y) >> 20], 1u);
        atomicAdd(&sh[fkey(v.z) >> 20], 1u);
        atomicAdd(&sh[fkey(v.w) >> 20], 1u);
    }
    __syncthreads();
    for (int i = t; i < NBINS; i += blockDim.x) {
        unsigned int v = sh[i];
        if (v) atomicAdd(&g_hist[b][i], v);
    }
}

// ---------------- 3. threshold bin (1 block / batch) ----------------
__global__ void k_selbin() {
    __shared__ unsigned int tsum[1024];
    int b = blockIdx.x, t = threadIdx.x;
    uint4 v = ((const uint4*)g_hist[b])[t];        // bins [4t,4t+4)
    tsum[t] = v.x + v.y + v.z + v.w;
    __syncthreads();
    if (t < 32) {
        unsigned int s = 0;
        for (int k = 0; k < 32; k++) s += tsum[t * 32 + k];
        unsigned int suf = s;                       // inclusive suffix over lanes
        for (int d = 1; d < 32; d <<= 1) {
            unsigned int x = __shfl_down_sync(0xFFFFFFFFu, suf, d);
            if (t + d < 32) suf += x;
        }
        unsigned int ball = __ballot_sync(0xFFFFFFFFu, suf >= TOPK);
        int L = 31 - __clz(ball);
        if (t == L) {
            unsigned int c = suf - s;               // sum over lanes > L
            int T = L * 32;
            for (int k = 31; k >= 0; k--) {
                c += tsum[L * 32 + k];
                if (c >= TOPK) { T = L * 32 + k; break; }
            }
            unsigned int c2 = c - tsum[T];
            int bin = 4 * T;
            for (int q = 3; q >= 0; q--) {
                c2 += g_hist[b][4 * T + q];
                if (c2 >= TOPK) { bin = 4 * T + q; break; }
            }
            g_bstar[b] = bin;
        }
    }
}

// ---------------- 4. gather candidates ----------------
__global__ void k_gather(const float* __restrict__ scores) {
    int b = blockIdx.y;
    int thr = g_bstar[b];
    const float4* s = (const float4*)(scores + (size_t)b * NELEM);
    for (int i = blockIdx.x * blockDim.x + threadIdx.x; i < NVEC4;
         i += gridDim.x * blockDim.x) {
        float4 v = s[i];
        float vv[4] = {v.x, v.y, v.z, v.w};
#pragma unroll
        for (int c = 0; c < 4; c++) {
            unsigned int u = fkey(vv[c]);
            if ((int)(u >> 20) >= thr) {
                int pos = atomicAdd(&g_cnt[b], 1);
                if (pos < CAP) {
                    unsigned int p = (unsigned int)(4 * i + c);
                    g_cand[b][pos] = ((unsigned long long)u << 32) | (~p);
                }
            }
        }
    }
}

// ---------------- 5. bitonic sort + fused deparametrize ----------------
__global__ void k_sortboxes(const float* __restrict__ bboxes) {
    __shared__ unsigned long long sk[CAP];
    int b = blockIdx.x, t = threadIdx.x;
    int cnt = g_cnt[b]; if (cnt > CAP) cnt = CAP;
    for (int i = t; i < CAP; i += blockDim.x)
        sk[i] = (i < cnt) ? g_cand[b][i] : 0ULL;
    __syncthreads();
    for (int k = 2; k <= CAP; k <<= 1) {
        for (int j = k >> 1; j > 0; j >>= 1) {
            for (int i = t; i < CAP; i += blockDim.x) {
                int l = i ^ j;
                if (l > i) {
                    unsigned long long a = sk[i], c = sk[l];
                    bool desc = ((i & k) == 0);
                    if (desc ? (a < c) : (a > c)) { sk[i] = c; sk[l] = a; }
                }
            }
            __syncthreads();
        }
    }
    // fused box deparametrization for the 2048 winners
    for (int row = t; row < TOPK; row += blockDim.x) {
        unsigned long long key = sk[row];
        unsigned int idx = ~(unsigned int)(key & 0xFFFFFFFFu);
        int d = idx / 9216;
        int rem = idx - d * 9216;
        int h = rem / 96;
        int w = rem - h * 96;
        float coord[3] = { (float)d + 0.5f, (float)h + 0.5f, (float)w + 0.5f };
        const float* bb = bboxes + (size_t)b * 6 * NELEM + idx;
        g_out7[b][row][0] = fkey_inv((unsigned int)(key >> 32));
        float vol = 1.0f;
#pragma unroll
        for (int c = 0; c < 3; c++) {
            float ctr = bb[(size_t)c * NELEM] * 12.0f + coord[c];
            float sz  = expf(bb[(size_t)(c + 3) * NELEM]) * 12.0f;
            g_out7[b][row][1 + c] = ctr;
            g_out7[b][row][4 + c] = sz;
            float half = sz * 0.5f;
            g_lo[b][row][c] = ctr - half;
            g_hi[b][row][c] = ctr + half;
            vol *= sz;
        }
        g_vol[b][row] = vol;
    }
}

// ---------------- 6. IoU suppression bitmask (transposed layout) ----------------
__global__ void k_mask() {
    int jw = blockIdx.x, itile = blockIdx.y, b = blockIdx.z;
    int t = threadIdx.x;
    int i = itile * 64 + t;
    if (jw < itile) { g_mask[b][jw][i] = 0ULL; return; }
    __shared__ float slo[64][3], shi[64][3], svol[64];
    int j0 = jw * 64;
#pragma unroll
    for (int c = 0; c < 3; c++) {
        slo[t][c] = g_lo[b][j0 + t][c];
        shi[t][c] = g_hi[b][j0 + t][c];
    }
    svol[t] = g_vol[b][j0 + t];
    __syncthreads();
    float lo0 = g_lo[b][i][0], lo1 = g_lo[b][i][1], lo2 = g_lo[b][i][2];
    float hi0 = g_hi[b][i][0], hi1 = g_hi[b][i][1], hi2 = g_hi[b][i][2];
    float voli = g_vol[b][i];
    unsigned long long bits = 0ULL;
#pragma unroll 8
    for (int jj = 0; jj < 64; jj++) {
        int j = j0 + jj;
        float t0 = fmaxf(fminf(hi0, shi[jj][0]) - fmaxf(lo0, slo[jj][0]), 0.0f);
        float t1 = fmaxf(fminf(hi1, shi[jj][1]) - fmaxf(lo1, slo[jj][1]), 0.0f);
        float t2 = fmaxf(fminf(hi2, shi[jj][2]) - fmaxf(lo2, slo[jj][2]), 0.0f);
        float inter = t0 * t1 * t2;
        float uni = voli + svol[jj] - inter;
        if ((j > i) && (inter / uni > 0.25f)) bits |= (1ULL << jj);
    }
    g_mask[b][jw][i] = bits;
}

// ---------------- 7. greedy reduce (1 warp) + fused output write ----------------
__global__ void k_reduceout(float* __restrict__ out) {
    __shared__ unsigned long long sdiag[32][64];   // diagonal 64x64 blocks, column word
    __shared__ unsigned long long skeep[32];
    int b = blockIdx.x, t = threadIdx.x;
    for (int e = t; e < 2048; e += blockDim.x) {
        int w = e >> 6, r = e & 63;
        sdiag[w][r] = g_mask[b][w][w * 64 + r];
    }
    __syncthreads();
    if (t < 32) {
        int lane = t;
        unsigned long long remv = 0ULL;
        for (int w = 0; w < 32; w++) {
            unsigned long long kept = 0ULL;
            if (lane == w) {
                unsigned long long a = ~remv;       // alive bits in my word
#pragma unroll 8
                for (int bit = 0; bit < 64; bit++) {
                    if ((a >> bit) & 1ULL) {
                        kept |= 1ULL << bit;
                        a &= ~sdiag[w][bit];
                    }
                }
            }
            kept = __shfl_sync(0xFFFFFFFFu, kept, w);   // one shfl per word
            const unsigned long long* col = &g_mask[b][lane][w * 64];
            unsigned long long a0 = 0, a1 = 0, a2 = 0, a3 = 0;
#pragma unroll
            for (int q = 0; q < 64; q += 4) {
                unsigned long long m0 = col[q], m1 = col[q + 1];
                unsigned long long m2 = col[q + 2], m3 = col[q + 3];
                if ((kept >> q) & 1ULL)       a0 |= m0;
                if ((kept >> (q + 1)) & 1ULL) a1 |= m1;
                if ((kept >> (q + 2)) & 1ULL) a2 |= m2;
                if ((kept >> (q + 3)) & 1ULL) a3 |= m3;
            }
            remv |= a0 | a1 | a2 | a3;
        }
        skeep[lane] = ~remv;
    }
    __syncthreads();
    for (int row = t; row < TOPK; row += blockDim.x) {
        bool keep = (skeep[row >> 6] >> (row & 63)) & 1ULL;
        float* o = out + ((size_t)b * TOPK + row) * 7;
#pragma unroll
        for (int c = 0; c < 7; c++) o[c] = keep ? g_out7[b][row][c] : 0.0f;
    }
}

extern "C" void kernel_launch(void* const* d_in, const int* in_sizes, int n_in,
                              void* d_out, int out_size) {
    const float* bboxes = (const float*)d_in[0];   // (2,6,64,96,96)
    const float* scores = (const float*)d_in[1];   // (2,64,96,96)
    float* out = (float*)d_out;                    // (2,2048,7)

    k_zero<<<8, 1024>>>();
    k_hist<<<dim3(72, BATCH), 1024>>>(scores);
    k_selbin<<<BATCH, 1024>>>();
    k_gather<<<dim3(72, BATCH), 1024>>>(scores);
    k_sortboxes<<<BATCH, 1024>>>(bboxes);
    k_mask<<<dim3(32, 32, BATCH), 64>>>();
    k_reduceout<<<BATCH, 1024>>>(out);
}

// round 6
// speedup vs baseline: 1.6455x; 1.1766x over previous
#include <cuda_runtime.h>

#define NELEM 589824      // 64*96*96
#define NVEC4 147456      // NELEM/4
#define BATCH 2
#define TOPK  2048
#define CAP   4096
#define NBINS 4096        // top-12-bit key histogram

// ---------------- device scratch ----------------
__device__ unsigned int        g_hist[BATCH][NBINS];   // zeroed at load; selbin re-zeroes
__device__ int                 g_cnt[BATCH];           // zeroed at load; mask re-zeroes
__device__ int                 g_bstar[BATCH];
__device__ unsigned long long  g_cand[BATCH][CAP];
__device__ float               g_out7[BATCH][TOPK][7];
__device__ float               g_lo[BATCH][TOPK][3];
__device__ float               g_hi[BATCH][TOPK][3];
__device__ float               g_vol[BATCH][TOPK];
__device__ unsigned long long  g_mask[BATCH][32][TOPK];   // [word][row]; lower triangle never touched

__device__ __forceinline__ unsigned int fkey(float f) {
    unsigned int b = __float_as_uint(f);
    unsigned int m = ((unsigned int)((int)b >> 31)) | 0x80000000u;
    return b ^ m;
}
__device__ __forceinline__ float fkey_inv(unsigned int u) {
    unsigned int b = (u & 0x80000000u) ? (u ^ 0x80000000u) : ~u;
    return __uint_as_float(b);
}

// ---------------- 1. histogram (warp-aggregated shared atomics) ----------------
__device__ __forceinline__ void hadd(unsigned int* sh, unsigned int bin) {
    unsigned int m = __match_any_sync(0xFFFFFFFFu, bin);
    if ((threadIdx.x & 31) == (unsigned)(__ffs(m) - 1))
        atomicAdd(&sh[bin], (unsigned int)__popc(m));
}
__global__ void k_hist(const float* __restrict__ scores) {
    __shared__ unsigned int sh[NBINS];
    int t = threadIdx.x;
    for (int i = t; i < NBINS; i += blockDim.x) sh[i] = 0u;
    __syncthreads();
    int b = blockIdx.y;
    const float4* s = (const float4*)(scores + (size_t)b * NELEM);
    int i = blockIdx.x * blockDim.x + t;          // grid exactly covers NVEC4
    float4 v = s[i];
    hadd(sh, fkey(v.x) >> 20);
    hadd(sh, fkey(v.y) >> 20);
    hadd(sh, fkey(v.z) >> 20);
    hadd(sh, fkey(v.w) >> 20);
    __syncthreads();
    for (int i2 = t; i2 < NBINS; i2 += blockDim.x) {
        unsigned int c = sh[i2];
        if (c) atomicAdd(&g_hist[b][i2], c);
    }
}

// ---------------- 2. threshold bin (1 block / batch); re-zeroes g_hist ----------------
__global__ void k_selbin() {
    __shared__ unsigned int sbin[NBINS];
    __shared__ unsigned int tsum[1024];
    int b = blockIdx.x, t = threadIdx.x;
    uint4 v = ((const uint4*)g_hist[b])[t];        // bins [4t,4t+4)
    ((uint4*)sbin)[t] = v;
    tsum[t] = v.x + v.y + v.z + v.w;
    ((uint4*)g_hist[b])[t] = make_uint4(0u, 0u, 0u, 0u);   // reset for next call
    __syncthreads();
    if (t < 32) {
        unsigned int s = 0;
        for (int k = 0; k < 32; k++) s += tsum[t * 32 + k];
        unsigned int suf = s;                       // inclusive suffix over lanes
        for (int d = 1; d < 32; d <<= 1) {
            unsigned int x = __shfl_down_sync(0xFFFFFFFFu, suf, d);
            if (t + d < 32) suf += x;
        }
        unsigned int ball = __ballot_sync(0xFFFFFFFFu, suf >= TOPK);
        int L = 31 - __clz(ball);
        if (t == L) {
            unsigned int c = suf - s;               // sum over lanes > L
            int T = L * 32;
            for (int k = 31; k >= 0; k--) {
                c += tsum[L * 32 + k];
                if (c >= TOPK) { T = L * 32 + k; break; }
            }
            unsigned int c2 = c - tsum[T];
            int bin = 4 * T;
            for (int q = 3; q >= 0; q--) {
                c2 += sbin[4 * T + q];
                if (c2 >= TOPK) { bin = 4 * T + q; break; }
            }
            g_bstar[b] = bin;
        }
    }
}

// ---------------- 3. gather candidates ----------------
__global__ void k_gather(const float* __restrict__ scores) {
    int b = blockIdx.y;
    int thr = g_bstar[b];
    const float4* s = (const float4*)(scores + (size_t)b * NELEM);
    int i = blockIdx.x * blockDim.x + threadIdx.x;
    float4 v = s[i];
    float vv[4] = {v.x, v.y, v.z, v.w};
#pragma unroll
    for (int c = 0; c < 4; c++) {
        unsigned int u = fkey(vv[c]);
        if ((int)(u >> 20) >= thr) {
            int pos = atomicAdd(&g_cnt[b], 1);
            if (pos < CAP) {
                unsigned int p = (unsigned int)(4 * i + c);
                g_cand[b][pos] = ((unsigned long long)u << 32) | (~p);
            }
        }
    }
}

// ---------------- 4. rank-scatter + fused deparametrize ----------------
// rank_i = #{j : key_j > key_i}; keys unique (idx in low bits) -> exact top-k order.
__global__ void k_rankbox(const float* __restrict__ bboxes) {
    __shared__ unsigned long long tile[256];
    int b = blockIdx.y, t = threadIdx.x;
    int cnt = g_cnt[b]; if (cnt > CAP) cnt = CAP;
    int c = blockIdx.x * 256 + t;
    unsigned long long ki = (c < cnt) ? g_cand[b][c] : 0ULL;
    int rank = 0;
    int nt = (cnt + 255) >> 8;
    for (int tt = 0; tt < nt; tt++) {
        int j = tt * 256 + t;
        tile[t] = (j < cnt) ? g_cand[b][j] : 0ULL;   // pad 0 never > any real key
        __syncthreads();
#pragma unroll 8
        for (int jj = 0; jj < 256; jj++)
            rank += (tile[jj] > ki);
        __syncthreads();
    }
    if (c < cnt && rank < TOPK) {
        int row = rank;
        unsigned int idx = ~(unsigned int)(ki & 0xFFFFFFFFu);
        int d = idx / 9216;
        int rem = idx - d * 9216;
        int h = rem / 96;
        int w = rem - h * 96;
        float coord[3] = { (float)d + 0.5f, (float)h + 0.5f, (float)w + 0.5f };
        const float* bb = bboxes + (size_t)b * 6 * NELEM + idx;
        g_out7[b][row][0] = fkey_inv((unsigned int)(ki >> 32));
        float vol = 1.0f;
#pragma unroll
        for (int q = 0; q < 3; q++) {
            float ctr = bb[(size_t)q * NELEM] * 12.0f + coord[q];
            float sz  = expf(bb[(size_t)(q + 3) * NELEM]) * 12.0f;
            g_out7[b][row][1 + q] = ctr;
            g_out7[b][row][4 + q] = sz;
            float half = sz * 0.5f;
            g_lo[b][row][q] = ctr - half;
            g_hi[b][row][q] = ctr + half;
            vol *= sz;
        }
        g_vol[b][row] = vol;
    }
}

// ---------------- 5. IoU suppression bitmask (upper triangle only) ----------------
__global__ void k_mask() {
    int jw = blockIdx.x, itile = blockIdx.y, b = blockIdx.z;
    int t = threadIdx.x;
    if (jw == 0 && itile == 0 && t == 0) g_cnt[b] = 0;   // reset for next call
    if (jw < itile) return;                              // lower triangle untouched
    int i = itile * 64 + t;
    __shared__ float slo[64][3], shi[64][3], svol[64];
    int j0 = jw * 64;
#pragma unroll
    for (int c = 0; c < 3; c++) {
        slo[t][c] = g_lo[b][j0 + t][c];
        shi[t][c] = g_hi[b][j0 + t][c];
    }
    svol[t] = g_vol[b][j0 + t];
    __syncthreads();
    float lo0 = g_lo[b][i][0], lo1 = g_lo[b][i][1], lo2 = g_lo[b][i][2];
    float hi0 = g_hi[b][i][0], hi1 = g_hi[b][i][1], hi2 = g_hi[b][i][2];
    float voli = g_vol[b][i];
    unsigned long long bits = 0ULL;
#pragma unroll 8
    for (int jj = 0; jj < 64; jj++) {
        int j = j0 + jj;
        float t0 = fmaxf(fminf(hi0, shi[jj][0]) - fmaxf(lo0, slo[jj][0]), 0.0f);
        float t1 = fmaxf(fminf(hi1, shi[jj][1]) - fmaxf(lo1, slo[jj][1]), 0.0f);
        float t2 = fmaxf(fminf(hi2, shi[jj][2]) - fmaxf(lo2, slo[jj][2]), 0.0f);
        float inter = t0 * t1 * t2;
        float uni = voli + svol[jj] - inter;
        float p = 0.25f * uni;                 // exactly representable scale
        bool sup = false;
        if (inter > p) {
            // only quotients within ~half-ulp above 0.25 can round down to 0.25 in
            // the reference's division; resolve that band with the exact division.
            if (inter < p * 1.000001f) sup = (inter / uni > 0.25f);
            else                       sup = true;
        }
        if (sup && (j > i)) bits |= (1ULL << jj);
    }
    g_mask[b][jw][i] = bits;
}

// ---------------- 6. greedy reduce (1 warp) + fused output write ----------------
__global__ void k_reduceout(float* __restrict__ out) {
    __shared__ unsigned long long sdiag[32][64];
    __shared__ unsigned long long skeep[32];
    int b = blockIdx.x, t = threadIdx.x;
    for (int e = t; e < 2048; e += blockDim.x) {
        int w = e >> 6, r = e & 63;
        sdiag[w][r] = g_mask[b][w][w * 64 + r];
    }
    __syncthreads();
    if (t < 32) {
        int lane = t;
        unsigned long long remv = 0ULL;
        for (int w = 0; w < 32; w++) {
            unsigned long long kept = 0ULL;
            if (lane == w) {
                unsigned long long a = ~remv;       // alive bits in my word
#pragma unroll 8
                for (int bit = 0; bit < 64; bit++) {
                    if ((a >> bit) & 1ULL) {
                        kept |= 1ULL << bit;
                        a &= ~sdiag[w][bit];
                    }
                }
            }
            kept = __shfl_sync(0xFFFFFFFFu, kept, w);   // one shfl per word
            if (lane >= w) {                            // lower triangle is all-zero
                const unsigned long long* col = &g_mask[b][lane][w * 64];
                unsigned long long a0 = 0, a1 = 0, a2 = 0, a3 = 0;
#pragma unroll
                for (int q = 0; q < 64; q += 4) {
                    unsigned long long m0 = col[q], m1 = col[q + 1];
                    unsigned long long m2 = col[q + 2], m3 = col[q + 3];
                    if ((kept >> q) & 1ULL)       a0 |= m0;
                    if ((kept >> (q + 1)) & 1ULL) a1 |= m1;
                    if ((kept >> (q + 2)) & 1ULL) a2 |= m2;
                    if ((kept >> (q + 3)) & 1ULL) a3 |= m3;
                }
                remv |= a0 | a1 | a2 | a3;
            }
        }
        skeep[lane] = ~remv;
    }
    __syncthreads();
    for (int row = t; row < TOPK; row += blockDim.x) {
        bool keep = (skeep[row >> 6] >> (row & 63)) & 1ULL;
        float* o = out + ((size_t)b * TOPK + row) * 7;
#pragma unroll
        for (int c = 0; c < 7; c++) o[c] = keep ? g_out7[b][row][c] : 0.0f;
    }
}

extern "C" void kernel_launch(void* const* d_in, const int* in_sizes, int n_in,
                              void* d_out, int out_size) {
    const float* bboxes = (const float*)d_in[0];   // (2,6,64,96,96)
    const float* scores = (const float*)d_in[1];   // (2,64,96,96)
    float* out = (float*)d_out;                    // (2,2048,7)

    k_hist<<<dim3(288, BATCH), 512>>>(scores);     // 288*512 == NVEC4 exactly
    k_selbin<<<BATCH, 1024>>>();
    k_gather<<<dim3(288, BATCH), 512>>>(scores);
    k_rankbox<<<dim3(16, BATCH), 256>>>(bboxes);   // 16*256 == CAP
    k_mask<<<dim3(32, 32, BATCH), 64>>>();
    k_reduceout<<<BATCH, 1024>>>(out);
}

// round 9
// speedup vs baseline: 1.8915x; 1.1495x over previous
#include <cuda_runtime.h>

#define NELEM 589824      // 64*96*96
#define NVEC4 147456      // NELEM/4
#define BATCH 2
#define TOPK  2048
#define CAP   4096
#define NBINS 4096        // top-12-bit key histogram
#define CTILES 16         // CAP/256
#define JTILES 16

// ---------------- device scratch ----------------
__device__ unsigned int        g_hist[BATCH][NBINS];   // zeroed at load; selbin re-zeroes
__device__ int                 g_cnt[BATCH];           // zeroed at load; mask re-zeroes
__device__ int                 g_bstar[BATCH];
__device__ int                 g_rank[BATCH][CAP];     // zeroed by selbin each replay
__device__ unsigned int       g_done[BATCH][CTILES];  // zeroed by selbin each replay
__device__ unsigned long long  g_cand[BATCH][CAP];
__device__ float               g_out7[BATCH][TOPK][7];
__device__ float               g_lo[BATCH][TOPK][3];
__device__ float               g_hi[BATCH][TOPK][3];
__device__ float               g_vol[BATCH][TOPK];
__device__ unsigned long long  g_mask[BATCH][32][TOPK];   // [word][row]; lower triangle untouched

__device__ __forceinline__ unsigned int fkey(float f) {
    unsigned int b = __float_as_uint(f);
    unsigned int m = ((unsigned int)((int)b >> 31)) | 0x80000000u;
    return b ^ m;
}
__device__ __forceinline__ float fkey_inv(unsigned int u) {
    unsigned int b = (u & 0x80000000u) ? (u ^ 0x80000000u) : ~u;
    return __uint_as_float(b);
}

// ---------------- 1. histogram (warp-aggregated shared atomics) ----------------
__device__ __forceinline__ void hadd(unsigned int* sh, unsigned int bin) {
    unsigned int m = __match_any_sync(0xFFFFFFFFu, bin);
    if ((threadIdx.x & 31) == (unsigned)(__ffs(m) - 1))
        atomicAdd(&sh[bin], (unsigned int)__popc(m));
}
__global__ void k_hist(const float* __restrict__ scores) {
    __shared__ unsigned int sh[NBINS];
    int t = threadIdx.x;
    for (int i = t; i < NBINS; i += blockDim.x) sh[i] = 0u;
    __syncthreads();
    int b = blockIdx.y;
    const float4* s = (const float4*)(scores + (size_t)b * NELEM);
    int i = blockIdx.x * blockDim.x + t;          // grid exactly covers NVEC4
    float4 v = s[i];
    hadd(sh, fkey(v.x) >> 20);
    hadd(sh, fkey(v.y) >> 20);
    hadd(sh, fkey(v.z) >> 20);
    hadd(sh, fkey(v.w) >> 20);
    __syncthreads();
    for (int i2 = t; i2 < NBINS; i2 += blockDim.x) {
        unsigned int c = sh[i2];
        if (c) atomicAdd(&g_hist[b][i2], c);
    }
}

// ---------------- 2. threshold bin (1 block / batch); re-zeroes scratch ----------------
__global__ void k_selbin() {
    __shared__ unsigned int sbin[NBINS];
    __shared__ unsigned int tsum[1024];
    int b = blockIdx.x, t = threadIdx.x;
    uint4 v = ((const uint4*)g_hist[b])[t];        // bins [4t,4t+4)
    ((uint4*)sbin)[t] = v;
    tsum[t] = v.x + v.y + v.z + v.w;
    ((uint4*)g_hist[b])[t] = make_uint4(0u, 0u, 0u, 0u);   // reset for next replay
    ((uint4*)g_rank[b])[t] = make_uint4(0u, 0u, 0u, 0u);   // 1024*uint4 == 4096 ints
    if (t < CTILES) g_done[b][t] = 0u;
    __syncthreads();
    if (t < 32) {
        unsigned int s = 0;
        for (int k = 0; k < 32; k++) s += tsum[t * 32 + k];
        unsigned int suf = s;                       // inclusive suffix over lanes
        for (int d = 1; d < 32; d <<= 1) {
            unsigned int x = __shfl_down_sync(0xFFFFFFFFu, suf, d);
            if (t + d < 32) suf += x;
        }
        unsigned int ball = __ballot_sync(0xFFFFFFFFu, suf >= TOPK);
        int L = 31 - __clz(ball);
        if (t == L) {
            unsigned int c = suf - s;               // sum over lanes > L
            int T = L * 32;
            for (int k = 31; k >= 0; k--) {
                c += tsum[L * 32 + k];
                if (c >= TOPK) { T = L * 32 + k; break; }
            }
            unsigned int c2 = c - tsum[T];
            int bin = 4 * T;
            for (int q = 3; q >= 0; q--) {
                c2 += sbin[4 * T + q];
                if (c2 >= TOPK) { bin = 4 * T + q; break; }
            }
            g_bstar[b] = bin;
        }
    }
}

// ---------------- 3. gather candidates ----------------
__global__ void k_gather(const float* __restrict__ scores) {
    int b = blockIdx.y;
    int thr = g_bstar[b];
    const float4* s = (const float4*)(scores + (size_t)b * NELEM);
    int i = blockIdx.x * blockDim.x + threadIdx.x;
    float4 v = s[i];
    float vv[4] = {v.x, v.y, v.z, v.w};
#pragma unroll
    for (int c = 0; c < 4; c++) {
        unsigned int u = fkey(vv[c]);
        if ((int)(u >> 20) >= thr) {
            int pos = atomicAdd(&g_cnt[b], 1);
            if (pos < CAP) {
                unsigned int p = (unsigned int)(4 * i + c);
                g_cand[b][pos] = ((unsigned long long)u << 32) | (~p);
            }
        }
    }
}

// ---------------- 4. tiled rank + last-block scatter/deparametrize ----------------
// rank_i = #{j : key_j > key_i}; keys unique (idx in low bits) -> exact top-k order.
__global__ void k_rankpart(const float* __restrict__ bboxes) {
    __shared__ unsigned long long tile[256];
    __shared__ bool sLast;
    int b = blockIdx.z, t = threadIdx.x;
    int ct = blockIdx.x, jt = blockIdx.y;
    int cnt = g_cnt[b]; if (cnt > CAP) cnt = CAP;
    int c = ct * 256 + t;
    unsigned long long ki = (c < cnt) ? g_cand[b][c] : 0ULL;
    int j = jt * 256 + t;
    tile[t] = (j < cnt) ? g_cand[b][j] : 0ULL;     // pad 0 never > any real key
    __syncthreads();
    if (c < cnt) {
        int r = 0;
#pragma unroll 16
        for (int jj = 0; jj < 256; jj++)
            r += (tile[jj] > ki);
        if (r) atomicAdd(&g_rank[b][c], r);
    }
    __syncthreads();
    if (t == 0) {
        __threadfence();                            // my block's rank adds -> visible
        unsigned int v = atomicAdd(&g_done[b][ct], 1u);
        sLast = (v == JTILES - 1);
        if (sLast) __threadfence();                 // acquire side
    }
    __syncthreads();
    if (!sLast) return;
    // last block for this ctile: all 16 jtile partials are in; scatter boxes.
    if (c < cnt) {
        int row = g_rank[b][c];
        if (row < TOPK) {
            unsigned int idx = ~(unsigned int)(ki & 0xFFFFFFFFu);
            int d = idx / 9216;
            int rem = idx - d * 9216;
            int h = rem / 96;
            int w = rem - h * 96;
            float coord[3] = { (float)d + 0.5f, (float)h + 0.5f, (float)w + 0.5f };
            const float* bb = bboxes + (size_t)b * 6 * NELEM + idx;
            g_out7[b][row][0] = fkey_inv((unsigned int)(ki >> 32));
            float vol = 1.0f;
#pragma unroll
            for (int q = 0; q < 3; q++) {
                float ctr = bb[(size_t)q * NELEM] * 12.0f + coord[q];
                float sz  = expf(bb[(size_t)(q + 3) * NELEM]) * 12.0f;
                g_out7[b][row][1 + q] = ctr;
                g_out7[b][row][4 + q] = sz;
                float half = sz * 0.5f;
                g_lo[b][row][q] = ctr - half;
                g_hi[b][row][q] = ctr + half;
                vol *= sz;
            }
            g_vol[b][row] = vol;
        }
    }
}

// ---------------- 5. IoU suppression bitmask (upper triangle only) ----------------
__global__ void k_mask() {
    int jw = blockIdx.x, itile = blockIdx.y, b = blockIdx.z;
    int t = threadIdx.x;
    if (jw == 0 && itile == 0 && t == 0) g_cnt[b] = 0;   // reset for next replay
    if (jw < itile) return;                              // lower triangle untouched
    int i = itile * 64 + t;
    __shared__ float slo[64][3], shi[64][3], svol[64];
    int j0 = jw * 64;
#pragma unroll
    for (int c = 0; c < 3; c++) {
        slo[t][c] = g_lo[b][j0 + t][c];
        shi[t][c] = g_hi[b][j0 + t][c];
    }
    svol[t] = g_vol[b][j0 + t];
    __syncthreads();
    float lo0 = g_lo[b][i][0], lo1 = g_lo[b][i][1], lo2 = g_lo[b][i][2];
    float hi0 = g_hi[b][i][0], hi1 = g_hi[b][i][1], hi2 = g_hi[b][i][2];
    float voli = g_vol[b][i];
    unsigned long long bits = 0ULL;
#pragma unroll 8
    for (int jj = 0; jj < 64; jj++) {
        int j = j0 + jj;
        float t0 = fmaxf(fminf(hi0, shi[jj][0]) - fmaxf(lo0, slo[jj][0]), 0.0f);
        float t1 = fmaxf(fminf(hi1, shi[jj][1]) - fmaxf(lo1, slo[jj][1]), 0.0f);
        float t2 = fmaxf(fminf(hi2, shi[jj][2]) - fmaxf(lo2, slo[jj][2]), 0.0f);
        float inter = t0 * t1 * t2;
        float uni = voli + svol[jj] - inter;
        float p = 0.25f * uni;                 // exactly representable scale
        bool sup = false;
        if (inter > p) {
            // quotients within ~half-ulp of 0.25: resolve with the exact division
            if (inter < p * 1.000001f) sup = (inter / uni > 0.25f);
            else                       sup = true;
        }
        if (sup && (j > i)) bits |= (1ULL << jj);
    }
    g_mask[b][jw][i] = bits;
}

// ---------------- 6. greedy reduce (1 warp) + fused output write ----------------
__global__ void k_reduceout(float* __restrict__ out) {
    __shared__ unsigned long long sdiag[32][64];
    __shared__ unsigned long long skeep[32];
    int b = blockIdx.x, t = threadIdx.x;
    for (int e = t; e < 2048; e += blockDim.x) {
        int w = e >> 6, r = e & 63;
        sdiag[w][r] = g_mask[b][w][w * 64 + r];
    }
    __syncthreads();
    if (t < 32) {
        int lane = t;
        unsigned long long remv = 0ULL;
        for (int w = 0; w < 32; w++) {
            unsigned long long kept = 0ULL;
            if (lane == w) {
                unsigned long long a = ~remv;       // alive bits in my word
#pragma unroll 8
                for (int bit = 0; bit < 64; bit++) {
                    if ((a >> bit) & 1ULL) {
                        kept |= 1ULL << bit;
                        a &= ~sdiag[w][bit];
                    }
                }
            }
            kept = __shfl_sync(0xFFFFFFFFu, kept, w);   // one shfl per word
            if (lane >= w) {                            // lower triangle is all-zero
                const unsigned long long* col = &g_mask[b][lane][w * 64];
                unsigned long long a0 = 0, a1 = 0, a2 = 0, a3 = 0;
#pragma unroll
                for (int q = 0; q < 64; q += 4) {
                    unsigned long long m0 = col[q], m1 = col[q + 1];
                    unsigned long long m2 = col[q + 2], m3 = col[q + 3];
                    if ((kept >> q) & 1ULL)       a0 |= m0;
                    if ((kept >> (q + 1)) & 1ULL) a1 |= m1;
                    if ((kept >> (q + 2)) & 1ULL) a2 |= m2;
                    if ((kept >> (q + 3)) & 1ULL) a3 |= m3;
                }
                remv |= a0 | a1 | a2 | a3;
            }
        }
        skeep[lane] = ~remv;
    }
    __syncthreads();
    for (int row = t; row < TOPK; row += blockDim.x) {
        bool keep = (skeep[row >> 6] >> (row & 63)) & 1ULL;
        float* o = out + ((size_t)b * TOPK + row) * 7;
#pragma unroll
        for (int c = 0; c < 7; c++) o[c] = keep ? g_out7[b][row][c] : 0.0f;
    }
}

extern "C" void kernel_launch(void* const* d_in, const int* in_sizes, int n_in,
                              void* d_out, int out_size) {
    const float* bboxes = (const float*)d_in[0];   // (2,6,64,96,96)
    const float* scores = (const float*)d_in[1];   // (2,64,96,96)
    float* out = (float*)d_out;                    // (2,2048,7)

    k_hist<<<dim3(288, BATCH), 512>>>(scores);     // 288*512 == NVEC4 exactly
    k_selbin<<<BATCH, 1024>>>();
    k_gather<<<dim3(288, BATCH), 512>>>(scores);
    k_rankpart<<<dim3(CTILES, JTILES, BATCH), 256>>>(bboxes);
    k_mask<<<dim3(32, 32, BATCH), 64>>>();
    k_reduceout<<<BATCH, 1024>>>(out);
}

// round 10
// speedup vs baseline: 2.6884x; 1.4213x over previous
#include <cuda_runtime.h>

#define NELEM 589824      // 64*96*96
#define NVEC4 147456      // NELEM/4
#define BATCH 2
#define TOPK  2048
#define CAP   4096
#define NBINS 4096        // top-12-bit key histogram
#define NBLK  148
#define NTHR  512

// ---------------- device scratch ----------------
__device__ unsigned int        g_hist[BATCH][NBINS];   // zeroed at load; selbin stage re-zeroes
__device__ int                 g_cnt[BATCH];           // zeroed at load; selbin stage re-zeroes
__device__ int                 g_bstar[BATCH];
__device__ int                 g_rank[BATCH][CAP];     // zeroed in selbin stage each call
__device__ unsigned long long  g_cand[BATCH][CAP];
__device__ float               g_out7[BATCH][TOPK][7];
__device__ float               g_lo[BATCH][TOPK][3];
__device__ float               g_hi[BATCH][TOPK][3];
__device__ float               g_vol[BATCH][TOPK];
__device__ unsigned long long  g_mask[BATCH][32][TOPK];   // [word][row]; lower triangle untouched
// grid barrier state (gen monotonically increases across calls; count returns to 0)
__device__ unsigned int        g_bar_cnt = 0;
__device__ unsigned int        g_bar_gen = 0;

__device__ __forceinline__ unsigned int fkey(float f) {
    unsigned int b = __float_as_uint(f);
    unsigned int m = ((unsigned int)((int)b >> 31)) | 0x80000000u;
    return b ^ m;
}
__device__ __forceinline__ float fkey_inv(unsigned int u) {
    unsigned int b = (u & 0x80000000u) ? (u ^ 0x80000000u) : ~u;
    return __uint_as_float(b);
}

// software grid barrier (all NBLK blocks co-resident: 148 blocks on >=148 SMs)
__device__ __forceinline__ void gsync() {
    __syncthreads();
    if (threadIdx.x == 0) {
        volatile unsigned int* genp = &g_bar_gen;
        unsigned int my = *genp;
        __threadfence();
        unsigned int ticket = atomicAdd(&g_bar_cnt, 1u);
        if (ticket == NBLK - 1) {
            g_bar_cnt = 0;
            __threadfence();
            atomicAdd(&g_bar_gen, 1u);
        } else {
            while (*genp == my) { }
        }
        __threadfence();
    }
    __syncthreads();
}

__device__ __forceinline__ void hadd(unsigned int* sh, unsigned int bin) {
    unsigned int m = __match_any_sync(0xFFFFFFFFu, bin);
    if ((threadIdx.x & 31) == (unsigned)(__ffs(m) - 1))
        atomicAdd(&sh[bin], (unsigned int)__popc(m));
}

__global__ void __launch_bounds__(NTHR, 1)
k_all(const float* __restrict__ bboxes, const float* __restrict__ scores,
      float* __restrict__ out) {
    __shared__ __align__(16) unsigned char sbuf[18688];
    const int bid = blockIdx.x, t = threadIdx.x;

    // ============ stage 1: histogram (74 blocks per batch) ============
    {
        unsigned int* sh = (unsigned int*)sbuf;
        for (int i = t; i < NBINS; i += NTHR) sh[i] = 0u;
        __syncthreads();
        int b = bid & 1, chunk = bid >> 1;
        const float4* s = (const float4*)(scores + (size_t)b * NELEM);
        for (int i = chunk * NTHR + t; i < NVEC4; i += 74 * NTHR) {
            float4 v = s[i];
            hadd(sh, fkey(v.x) >> 20);
            hadd(sh, fkey(v.y) >> 20);
            hadd(sh, fkey(v.z) >> 20);
            hadd(sh, fkey(v.w) >> 20);
        }
        __syncthreads();
        for (int i = t; i < NBINS; i += NTHR) {
            unsigned int c = sh[i];
            if (c) atomicAdd(&g_hist[b][i], c);
        }
    }
    gsync();

    // ============ stage 2: threshold bin + scratch reset (blocks 0,1) ============
    if (bid < BATCH) {
        int b = bid;
        unsigned int* sbin = (unsigned int*)sbuf;            // 4096
        unsigned int* tsum = (unsigned int*)(sbuf + 16384);  // 512
        uint4 z4 = make_uint4(0u, 0u, 0u, 0u);
        uint4 v0 = ((const uint4*)g_hist[b])[2 * t];
        uint4 v1 = ((const uint4*)g_hist[b])[2 * t + 1];
        ((uint4*)sbin)[2 * t] = v0;
        ((uint4*)sbin)[2 * t + 1] = v1;
        tsum[t] = v0.x + v0.y + v0.z + v0.w + v1.x + v1.y + v1.z + v1.w;
        ((uint4*)g_hist[b])[2 * t] = z4;                     // reset for next call
        ((uint4*)g_hist[b])[2 * t + 1] = z4;
        ((uint4*)g_rank[b])[2 * t] = z4;                     // zero 4096 ranks
        ((uint4*)g_rank[b])[2 * t + 1] = z4;
        if (t == 0) g_cnt[b] = 0;
        __syncthreads();
        if (t < 32) {
            unsigned int s = 0;
            for (int k = 0; k < 16; k++) s += tsum[t * 16 + k];
            unsigned int suf = s;
            for (int d = 1; d < 32; d <<= 1) {
                unsigned int x = __shfl_down_sync(0xFFFFFFFFu, suf, d);
                if (t + d < 32) suf += x;
            }
            unsigned int ball = __ballot_sync(0xFFFFFFFFu, suf >= TOPK);
            int L = 31 - __clz(ball);
            if (t == L) {
                unsigned int c = suf - s;
                int T = L * 16;
                for (int k = 15; k >= 0; k--) {
                    c += tsum[L * 16 + k];
                    if (c >= TOPK) { T = L * 16 + k; break; }
                }
                unsigned int c2 = c - tsum[T];
                int bin = 8 * T;
                for (int q = 7; q >= 0; q--) {
                    c2 += sbin[8 * T + q];
                    if (c2 >= TOPK) { bin = 8 * T + q; break; }
                }
                g_bstar[b] = bin;
            }
        }
    }
    gsync();

    // ============ stage 3: gather candidates ============
    {
        int b = bid & 1, chunk = bid >> 1;
        int thr = g_bstar[b];
        const float4* s = (const float4*)(scores + (size_t)b * NELEM);
        for (int i = chunk * NTHR + t; i < NVEC4; i += 74 * NTHR) {
            float4 v = s[i];
            float vv[4] = {v.x, v.y, v.z, v.w};
#pragma unroll
            for (int c = 0; c < 4; c++) {
                unsigned int u = fkey(vv[c]);
                if ((int)(u >> 20) >= thr) {
                    int pos = atomicAdd(&g_cnt[b], 1);
                    if (pos < CAP) {
                        unsigned int p = (unsigned int)(4 * i + c);
                        g_cand[b][pos] = ((unsigned long long)u << 32) | (~p);
                    }
                }
            }
        }
    }
    gsync();

    // ============ stage 4: tiled rank (512x512 tiles, 128 jobs) ============
    if (bid < 128) {
        int b = bid >> 6, r = bid & 63, ct = r >> 3, jt = r & 7;
        int cnt = __ldcg(&g_cnt[b]); if (cnt > CAP) cnt = CAP;
        unsigned long long* tile = (unsigned long long*)sbuf;   // 512*8 = 4KB
        int c = ct * 512 + t;
        unsigned long long ki = (c < cnt) ? g_cand[b][c] : 0ULL;
        int j = jt * 512 + t;
        tile[t] = (j < cnt) ? g_cand[b][j] : 0ULL;
        __syncthreads();
        if (c < cnt) {
            int rk = 0;
#pragma unroll 16
            for (int jj = 0; jj < 512; jj++)
                rk += (tile[jj] > ki);
            if (rk) atomicAdd(&g_rank[b][c], rk);
        }
    }
    gsync();

    // ============ stage 5: scatter + deparametrize (8192 candidates) ============
    {
        int gid = bid * NTHR + t;
        if (gid < BATCH * CAP) {
            int b = gid >> 12, c = gid & (CAP - 1);
            int cnt = __ldcg(&g_cnt[b]); if (cnt > CAP) cnt = CAP;
            if (c < cnt) {
                unsigned long long ki = g_cand[b][c];
                int row = __ldcg(&g_rank[b][c]);
                if (row < TOPK) {
                    unsigned int idx = ~(unsigned int)(ki & 0xFFFFFFFFu);
                    int d = idx / 9216;
                    int rem = idx - d * 9216;
                    int h = rem / 96;
                    int w = rem - h * 96;
                    float coord[3] = { (float)d + 0.5f, (float)h + 0.5f, (float)w + 0.5f };
                    const float* bb = bboxes + (size_t)b * 6 * NELEM + idx;
                    g_out7[b][row][0] = fkey_inv((unsigned int)(ki >> 32));
                    float vol = 1.0f;
#pragma unroll
                    for (int q = 0; q < 3; q++) {
                        float ctr = bb[(size_t)q * NELEM] * 12.0f + coord[q];
                        float sz  = expf(bb[(size_t)(q + 3) * NELEM]) * 12.0f;
                        g_out7[b][row][1 + q] = ctr;
                        g_out7[b][row][4 + q] = sz;
                        float half = sz * 0.5f;
                        g_lo[b][row][q] = ctr - half;
                        g_hi[b][row][q] = ctr + half;
                        vol *= sz;
                    }
                    g_vol[b][row] = vol;
                }
            }
        }
    }
    gsync();

    // ============ stage 6: IoU bitmask, upper triangle (1056 jobs of 64 threads) ====
    {
        int g = t >> 6, l64 = t & 63;
        int slot = bid * 8 + g;
        bool act = slot < 1056;
        int b = 0, itile = 0, jw = 0;
        if (act) {
            b = slot / 528;
            int r = slot - b * 528;
            int it = 0;
            while (r >= 32 - it) { r -= 32 - it; it++; }
            itile = it; jw = it + r;
        }
        float* sj = (float*)sbuf + g * 448;     // 64 boxes * 7 floats per group
        if (act) {
            int j = jw * 64 + l64;
            sj[l64 * 7 + 0] = g_lo[b][j][0];
            sj[l64 * 7 + 1] = g_lo[b][j][1];
            sj[l64 * 7 + 2] = g_lo[b][j][2];
            sj[l64 * 7 + 3] = g_hi[b][j][0];
            sj[l64 * 7 + 4] = g_hi[b][j][1];
            sj[l64 * 7 + 5] = g_hi[b][j][2];
            sj[l64 * 7 + 6] = g_vol[b][j];
        }
        __syncthreads();
        if (act) {
            int i = itile * 64 + l64;
            float lo0 = g_lo[b][i][0], lo1 = g_lo[b][i][1], lo2 = g_lo[b][i][2];
            float hi0 = g_hi[b][i][0], hi1 = g_hi[b][i][1], hi2 = g_hi[b][i][2];
            float voli = g_vol[b][i];
            int j0 = jw * 64;
            unsigned long long bits = 0ULL;
#pragma unroll 8
            for (int jj = 0; jj < 64; jj++) {
                int j = j0 + jj;
                const float* p = sj + jj * 7;
                float t0 = fmaxf(fminf(hi0, p[3]) - fmaxf(lo0, p[0]), 0.0f);
                float t1 = fmaxf(fminf(hi1, p[4]) - fmaxf(lo1, p[1]), 0.0f);
                float t2 = fmaxf(fminf(hi2, p[5]) - fmaxf(lo2, p[2]), 0.0f);
                float inter = t0 * t1 * t2;
                float uni = voli + p[6] - inter;
                float q = 0.25f * uni;              // exactly representable scale
                bool sup = false;
                if (inter > q) {
                    if (inter < q * 1.000001f) sup = (inter / uni > 0.25f);
                    else                       sup = true;
                }
                if (sup && (j > i)) bits |= (1ULL << jj);
            }
            g_mask[b][jw][i] = bits;
        }
    }
    gsync();

    // ============ stage 7: greedy reduce + output (blocks 0,1) ============
    if (bid < BATCH) {
        int b = bid;
        unsigned long long (*sdiag)[64] = (unsigned long long (*)[64])sbuf;  // 16KB
        unsigned long long* skeep = (unsigned long long*)(sbuf + 16384);
        for (int e = t; e < 2048; e += NTHR) {
            int w = e >> 6, r = e & 63;
            sdiag[w][r] = g_mask[b][w][w * 64 + r];
        }
        __syncthreads();
        if (t < 32) {
            int lane = t;
            unsigned long long remv = 0ULL;
            for (int w = 0; w < 32; w++) {
                unsigned long long kept = 0ULL;
                if (lane == w) {
                    unsigned long long a = ~remv;
#pragma unroll 8
                    for (int bit = 0; bit < 64; bit++) {
                        if ((a >> bit) & 1ULL) {
                            kept |= 1ULL << bit;
                            a &= ~sdiag[w][bit];
                        }
                    }
                }
                kept = __shfl_sync(0xFFFFFFFFu, kept, w);
                if (lane >= w) {
                    const unsigned long long* col = &g_mask[b][lane][w * 64];
                    unsigned long long a0 = 0, a1 = 0, a2 = 0, a3 = 0;
#pragma unroll
                    for (int q = 0; q < 64; q += 4) {
                        unsigned long long m0 = col[q], m1 = col[q + 1];
                        unsigned long long m2 = col[q + 2], m3 = col[q + 3];
                        if ((kept >> q) & 1ULL)       a0 |= m0;
                        if ((kept >> (q + 1)) & 1ULL) a1 |= m1;
                        if ((kept >> (q + 2)) & 1ULL) a2 |= m2;
                        if ((kept >> (q + 3)) & 1ULL) a3 |= m3;
                    }
                    remv |= a0 | a1 | a2 | a3;
                }
            }
            skeep[lane] = ~remv;
        }
        __syncthreads();
        for (int row = t; row < TOPK; row += NTHR) {
            bool keep = (skeep[row >> 6] >> (row & 63)) & 1ULL;
            float* o = out + ((size_t)b * TOPK + row) * 7;
#pragma unroll
            for (int c = 0; c < 7; c++) o[c] = keep ? g_out7[b][row][c] : 0.0f;
        }
    }
}

extern "C" void kernel_launch(void* const* d_in, const int* in_sizes, int n_in,
                              void* d_out, int out_size) {
    const float* bboxes = (const float*)d_in[0];   // (2,6,64,96,96)
    const float* scores = (const float*)d_in[1];   // (2,64,96,96)
    float* out = (float*)d_out;                    // (2,2048,7)
    k_all<<<NBLK, NTHR>>>(bboxes, scores, out);
}